// round 4
// baseline (speedup 1.0000x reference)
#include <cuda_runtime.h>
#include <math.h>

#define N_BINS 15

// Scratch accumulators (no allocation allowed -> __device__ globals).
__device__ float g_conf_sum[N_BINS];
__device__ float g_acc_sum[N_BINS];
__device__ float g_count[N_BINS];

__global__ void ece_zero_kernel() {
    float* base = g_conf_sum;   // arrays are contiguous per-symbol; zero each explicitly
    int i = threadIdx.x;
    if (i < N_BINS) {
        g_conf_sum[i] = 0.0f;
        g_acc_sum[i]  = 0.0f;
        g_count[i]    = 0.0f;
    }
    (void)base;
}

__global__ __launch_bounds__(256) void ece_main_kernel(
    const float* __restrict__ logits,   // [n, 32] fp32
    const int* __restrict__ labels,     // [n] int32 (JAX downcasts int64 w/o x64)
    int n)
{
    __shared__ float s_conf[N_BINS];
    __shared__ float s_acc[N_BINS];
    __shared__ float s_cnt[N_BINS];

    int t = threadIdx.x;
    if (t < N_BINS) {
        s_conf[t] = 0.0f;
        s_acc[t]  = 0.0f;
        s_cnt[t]  = 0.0f;
    }
    __syncthreads();

    int stride = gridDim.x * blockDim.x;
    for (int i = blockIdx.x * blockDim.x + t; i < n; i += stride) {
        const float4* row = reinterpret_cast<const float4*>(logits) + (size_t)i * 8;
        float4 v[8];
        #pragma unroll
        for (int k = 0; k < 8; k++) v[k] = __ldg(row + k);

        // max over 32
        float m = v[0].x;
        #pragma unroll
        for (int k = 0; k < 8; k++) {
            m = fmaxf(m, v[k].x);
            m = fmaxf(m, v[k].y);
            m = fmaxf(m, v[k].z);
            m = fmaxf(m, v[k].w);
        }

        // sum of exp(x - m)
        float s = 0.0f;
        #pragma unroll
        for (int k = 0; k < 8; k++) {
            s += __expf(v[k].x - m);
            s += __expf(v[k].y - m);
            s += __expf(v[k].z - m);
            s += __expf(v[k].w - m);
        }
        float conf = 1.0f / s;   // max softmax prob

        // accuracy: pred == label  <=>  logits[label] == max (distinct values)
        int lab = labels[i];
        lab = max(0, min(31, lab));           // defensive clamp: never OOB
        float xl = __ldg(logits + (size_t)i * 32 + lab);
        float acc = (xl == m) ? 1.0f : 0.0f;

        // equal-width bin over (0, 1]: bin b covers (b/15, (b+1)/15]
        int b = (int)ceilf(conf * (float)N_BINS) - 1;
        b = max(0, min(N_BINS - 1, b));

        atomicAdd(&s_conf[b], conf);
        atomicAdd(&s_acc[b],  acc);
        atomicAdd(&s_cnt[b],  1.0f);
    }
    __syncthreads();

    if (t < N_BINS) {
        if (s_cnt[t] != 0.0f) {
            atomicAdd(&g_conf_sum[t], s_conf[t]);
            atomicAdd(&g_acc_sum[t],  s_acc[t]);
            atomicAdd(&g_count[t],    s_cnt[t]);
        }
    }
}

__global__ void ece_finalize_kernel(float* __restrict__ out, float n_total) {
    if (threadIdx.x == 0 && blockIdx.x == 0) {
        float ece = 0.0f;
        float nt = fmaxf(n_total, 1.0f);
        #pragma unroll
        for (int b = 0; b < N_BINS; b++) {
            float c = g_count[b];
            if (c > 0.0f) {
                float gap = fabsf(g_conf_sum[b] / c - g_acc_sum[b] / c);
                ece += gap * (c / nt);
            }
        }
        out[0] = ece;
    }
}

extern "C" void kernel_launch(void* const* d_in, const int* in_sizes, int n_in,
                              void* d_out, int out_size) {
    const float* logits = (const float*)d_in[0];
    const int* labels   = (const int*)d_in[1];
    int n = in_sizes[1];            // number of rows (labels count)

    ece_zero_kernel<<<1, 32>>>();

    int threads = 256;
    int blocks = (n + threads - 1) / threads;
    if (blocks > 8192) blocks = 8192;
    if (blocks < 1) blocks = 1;
    ece_main_kernel<<<blocks, threads>>>(logits, labels, n);

    ece_finalize_kernel<<<1, 32>>>((float*)d_out, (float)n);
}

// round 5
// speedup vs baseline: 1.3703x; 1.3703x over previous
#include <cuda_runtime.h>
#include <math.h>

#define N_BINS 15

__device__ float g_conf_sum[N_BINS];
__device__ float g_acc_sum[N_BINS];
__device__ float g_count[N_BINS];

__global__ void ece_zero_kernel() {
    int i = threadIdx.x;
    if (i < N_BINS) {
        g_conf_sum[i] = 0.0f;
        g_acc_sum[i]  = 0.0f;
        g_count[i]    = 0.0f;
    }
}

__global__ __launch_bounds__(256) void ece_main_kernel(
    const float* __restrict__ logits,   // [n, 32] fp32
    const int* __restrict__ labels,     // [n] int32
    int n)
{
    __shared__ float s_conf[N_BINS];
    __shared__ float s_acc[N_BINS];
    __shared__ float s_cnt[N_BINS];

    int t = threadIdx.x;
    if (t < N_BINS) {
        s_conf[t] = 0.0f;
        s_acc[t]  = 0.0f;
        s_cnt[t]  = 0.0f;
    }
    __syncthreads();

    const float4* logits4 = reinterpret_cast<const float4*>(logits);

    int lane = t & 31;
    int sub  = lane >> 3;          // which of the 4 rows this lane helps with
    int part = lane & 7;           // which float4 of the row (8 x float4 = 32 floats)

    int warpId  = (blockIdx.x * blockDim.x + t) >> 5;
    int nWarps  = (gridDim.x * blockDim.x) >> 5;
    int nChunks = (n + 3) >> 2;    // 4 rows per warp-iteration

    for (int c = warpId; c < nChunks; c += nWarps) {
        int row = c * 4 + sub;
        bool valid = row < n;

        // Warp accesses 512B contiguous per LDG.128 (4 lines) — fully coalesced.
        float4 v = make_float4(0.f, 0.f, 0.f, 0.f);
        int lab = -1;
        if (valid) {
            v = __ldg(logits4 + (size_t)row * 8 + part);
            lab = labels[row];     // 8 lanes broadcast-load the same word
        }

        // row max: local max of 4, then butterfly over the 8-lane group
        float m = fmaxf(fmaxf(v.x, v.y), fmaxf(v.z, v.w));
        m = fmaxf(m, __shfl_xor_sync(0xffffffffu, m, 1));
        m = fmaxf(m, __shfl_xor_sync(0xffffffffu, m, 2));
        m = fmaxf(m, __shfl_xor_sync(0xffffffffu, m, 4));

        // sum exp(x - m) (max element contributes exactly 1)
        float e = __expf(v.x - m) + __expf(v.y - m)
                + __expf(v.z - m) + __expf(v.w - m);

        // accuracy flag: does the label column hold the max?
        // (argmax softmax == argmax logits; values distinct w.p. 1)
        int base = part * 4;
        float f = 0.0f;
        f += (v.x == m && base + 0 == lab) ? 1.0f : 0.0f;
        f += (v.y == m && base + 1 == lab) ? 1.0f : 0.0f;
        f += (v.z == m && base + 2 == lab) ? 1.0f : 0.0f;
        f += (v.w == m && base + 3 == lab) ? 1.0f : 0.0f;

        e += __shfl_xor_sync(0xffffffffu, e, 1);
        f += __shfl_xor_sync(0xffffffffu, f, 1);
        e += __shfl_xor_sync(0xffffffffu, e, 2);
        f += __shfl_xor_sync(0xffffffffu, f, 2);
        e += __shfl_xor_sync(0xffffffffu, e, 4);
        f += __shfl_xor_sync(0xffffffffu, f, 4);

        if (part == 0 && valid) {
            float conf = 1.0f / e;              // max softmax probability
            // bin b covers (b/15, (b+1)/15]
            int b = (int)ceilf(conf * (float)N_BINS) - 1;
            b = max(0, min(N_BINS - 1, b));
            atomicAdd(&s_conf[b], conf);
            atomicAdd(&s_acc[b],  f);
            atomicAdd(&s_cnt[b],  1.0f);
        }
    }
    __syncthreads();

    if (t < N_BINS) {
        if (s_cnt[t] != 0.0f) {
            atomicAdd(&g_conf_sum[t], s_conf[t]);
            atomicAdd(&g_acc_sum[t],  s_acc[t]);
            atomicAdd(&g_count[t],    s_cnt[t]);
        }
    }
}

__global__ void ece_finalize_kernel(float* __restrict__ out, float n_total) {
    if (threadIdx.x == 0 && blockIdx.x == 0) {
        float ece = 0.0f;
        float nt = fmaxf(n_total, 1.0f);
        #pragma unroll
        for (int b = 0; b < N_BINS; b++) {
            float c = g_count[b];
            if (c > 0.0f) {
                float gap = fabsf(g_conf_sum[b] / c - g_acc_sum[b] / c);
                ece += gap * (c / nt);
            }
        }
        out[0] = ece;
    }
}

extern "C" void kernel_launch(void* const* d_in, const int* in_sizes, int n_in,
                              void* d_out, int out_size) {
    const float* logits = (const float*)d_in[0];
    const int* labels   = (const int*)d_in[1];
    int n = in_sizes[1];

    ece_zero_kernel<<<1, 32>>>();

    // 2048 blocks x 256 thr = 16384 warps; each warp strides over 4-row chunks.
    // Adjacent warps touch adjacent 512B spans -> coalesced across the grid.
    int threads = 256;
    int blocks = 2048;
    ece_main_kernel<<<blocks, threads>>>(logits, labels, n);

    ece_finalize_kernel<<<1, 32>>>((float*)d_out, (float)n);
}

// round 7
// speedup vs baseline: 1.6063x; 1.1723x over previous
#include <cuda_runtime.h>
#include <math.h>

#define N_BINS 15
#define N_ACC  45                 // [0:15) conf_sum, [15:30) acc_sum, [30:45) count
#define NBLK   1184               // 148 SMs x 8 blocks of 256 (full occupancy, 1 wave)

// Scratch (no allocation allowed -> __device__ globals).
__device__ float g_part[N_ACC * NBLK];    // [acc][block] for coalesced final read
__device__ unsigned int g_ticket;         // zero at load; last block resets -> replay-safe

__global__ __launch_bounds__(256) void ece_fused_kernel(
    const float* __restrict__ logits,   // [n, 32] fp32
    const int* __restrict__ labels,     // [n] int32
    float* __restrict__ out,
    int n)
{
    // 32 per-(warp,sub) private accumulator slots: no atomics in the hot loop.
    __shared__ float s_priv[32 * N_ACC];   // stride 45 (odd) -> 4 subs hit distinct banks
    __shared__ float s_final[N_ACC];
    __shared__ unsigned int s_isLast;

    int t = threadIdx.x;
    for (int i = t; i < 32 * N_ACC; i += 256) s_priv[i] = 0.0f;
    if (t < N_ACC) s_final[t] = 0.0f;
    __syncthreads();

    const float4* logits4 = reinterpret_cast<const float4*>(logits);

    int lane = t & 31;
    int sub  = lane >> 3;          // which of 4 rows in the chunk
    int part = lane & 7;           // which float4 of the row
    int wInB = t >> 5;             // warp index in block (0..7)
    float* myBins = &s_priv[(wInB * 4 + sub) * N_ACC];

    int warpId  = (blockIdx.x * blockDim.x + t) >> 5;
    int nWarps  = (gridDim.x * blockDim.x) >> 5;
    int nChunks = (n + 3) >> 2;    // 4 rows per warp-iteration

    for (int c = warpId; c < nChunks; c += nWarps) {
        int row = c * 4 + sub;
        bool valid = row < n;

        float4 v = make_float4(-1e30f, -1e30f, -1e30f, -1e30f);
        int lab = -1;
        if (valid) {
            v = __ldg(logits4 + (size_t)row * 8 + part);   // 512B/warp, coalesced
            lab = labels[row];
        }

        // row max over the 8-lane group
        float m = fmaxf(fmaxf(v.x, v.y), fmaxf(v.z, v.w));
        m = fmaxf(m, __shfl_xor_sync(0xffffffffu, m, 1));
        m = fmaxf(m, __shfl_xor_sync(0xffffffffu, m, 2));
        m = fmaxf(m, __shfl_xor_sync(0xffffffffu, m, 4));

        // sum exp(x - m)
        float e = __expf(v.x - m) + __expf(v.y - m)
                + __expf(v.z - m) + __expf(v.w - m);

        // pred == label  <=>  label column holds the row max
        int base = part * 4;
        float f = 0.0f;
        f += (v.x == m && base + 0 == lab) ? 1.0f : 0.0f;
        f += (v.y == m && base + 1 == lab) ? 1.0f : 0.0f;
        f += (v.z == m && base + 2 == lab) ? 1.0f : 0.0f;
        f += (v.w == m && base + 3 == lab) ? 1.0f : 0.0f;

        e += __shfl_xor_sync(0xffffffffu, e, 1);
        f += __shfl_xor_sync(0xffffffffu, f, 1);
        e += __shfl_xor_sync(0xffffffffu, e, 2);
        f += __shfl_xor_sync(0xffffffffu, f, 2);
        e += __shfl_xor_sync(0xffffffffu, e, 4);
        f += __shfl_xor_sync(0xffffffffu, f, 4);

        if (part == 0 && valid) {
            float conf = 1.0f / e;
            int b = __float2int_ru(conf * (float)N_BINS) - 1;   // (b/15,(b+1)/15]
            b = max(0, min(N_BINS - 1, b));
            myBins[b]              += conf;    // plain smem RMW, conflict-free
            myBins[N_BINS + b]     += f;
            myBins[2 * N_BINS + b] += 1.0f;
        }
    }
    __syncthreads();

    // Reduce 32 private slots -> 45 block partials; write [acc][block].
    if (t < N_ACC) {
        float s = 0.0f;
        #pragma unroll
        for (int sl = 0; sl < 32; sl++) s += s_priv[sl * N_ACC + t];
        g_part[t * NBLK + blockIdx.x] = s;
    }
    __syncthreads();
    __threadfence();
    if (t == 0) {
        unsigned int tk = atomicAdd(&g_ticket, 1u);
        s_isLast = (tk == gridDim.x - 1) ? 1u : 0u;
    }
    __syncthreads();

    if (s_isLast) {
        if (t == 0) g_ticket = 0;   // reset for next graph replay (deterministic)

        // 225 threads: 5 per accumulator, strided over blocks, coalesced __ldcg.
        if (t < 225) {
            int a = t / 5, j0 = t % 5;
            const float* src = &g_part[a * NBLK];
            float s = 0.0f;
            for (int j = j0; j < (int)gridDim.x; j += 5) s += __ldcg(src + j);
            atomicAdd(&s_final[a], s);   // 45 addresses x 5 lanes: trivial
        }
        __syncthreads();

        if (t == 0) {
            float nt = fmaxf((float)n, 1.0f);
            float ece = 0.0f;
            #pragma unroll
            for (int b = 0; b < N_BINS; b++) {
                float c = s_final[2 * N_BINS + b];
                if (c > 0.0f) {
                    float gap = fabsf(s_final[b] / c - s_final[N_BINS + b] / c);
                    ece += gap * (c / nt);
                }
            }
            out[0] = ece;
        }
    }
}

extern "C" void kernel_launch(void* const* d_in, const int* in_sizes, int n_in,
                              void* d_out, int out_size) {
    const float* logits = (const float*)d_in[0];
    const int* labels   = (const int*)d_in[1];
    int n = in_sizes[1];

    ece_fused_kernel<<<NBLK, 256>>>(logits, labels, (float*)d_out, n);
}